// round 3
// baseline (speedup 1.0000x reference)
#include <cuda_runtime.h>
#include <cuda_fp16.h>
#include <cstdint>

// ---------------- problem dims ----------------
#define MDIM 8192
#define KDIM 4096
#define NDIM 11008
#define NGROUPS 32

// ---------------- GEMM tiling (HMMA mma.sync path; compute_100-safe) --------
#define BM 128
#define BN 128
#define BKQ 32
#define STAGES 4
#define KITERS (KDIM / BKQ)          // 128
#define LDS_ROW (BKQ + 8)            // 40 halves = 80B row stride (conflict-free ldmatrix)
#define A_SM_BYTES (BM * LDS_ROW * 2)      // 10240
#define B_SM_BYTES (BN * LDS_ROW * 2)      // 10240
#define STAGE_BYTES (A_SM_BYTES + B_SM_BYTES)   // 20480
#define SMEM_TOTAL (STAGES * STAGE_BYTES)       // 81920

// ---------------- scratch (device globals; no allocs allowed) ----------------
__device__ __align__(1024) __half g_wt[(size_t)NDIM * KDIM];  // W^T, (N,K) K-major fp16
__device__ __align__(1024) __half g_x[(size_t)MDIM * KDIM];   // x fp16, (M,K) K-major

// ---------------- PTX helpers (all family-common features) ----------------
__device__ __forceinline__ uint32_t smem_u32(const void* p) {
    uint32_t a;
    asm("{ .reg .u64 t; cvta.to.shared.u64 t, %1; cvt.u32.u64 %0, t; }" : "=r"(a) : "l"(p));
    return a;
}
__device__ __forceinline__ void cp_async16(uint32_t dst, const void* src) {
    asm volatile("cp.async.cg.shared.global [%0], [%1], 16;" :: "r"(dst), "l"(src));
}
__device__ __forceinline__ void cp_commit() {
    asm volatile("cp.async.commit_group;");
}
__device__ __forceinline__ void ldsm_x4(uint32_t* r, uint32_t a) {
    asm volatile("ldmatrix.sync.aligned.m8n8.x4.shared.b16 {%0,%1,%2,%3}, [%4];"
                 : "=r"(r[0]), "=r"(r[1]), "=r"(r[2]), "=r"(r[3]) : "r"(a));
}
__device__ __forceinline__ void mma16816(float* d, const uint32_t* a, const uint32_t* b) {
    asm volatile(
        "mma.sync.aligned.m16n8k16.row.col.f32.f16.f16.f32 "
        "{%0,%1,%2,%3}, {%4,%5,%6,%7}, {%8,%9}, {%0,%1,%2,%3};"
        : "+f"(d[0]), "+f"(d[1]), "+f"(d[2]), "+f"(d[3])
        : "r"(a[0]), "r"(a[1]), "r"(a[2]), "r"(a[3]), "r"(b[0]), "r"(b[1]));
}

// ---------------- kernel 1: x fp32 -> fp16 ----------------
__global__ void convert_x_kernel(const float* __restrict__ x) {
    size_t i = (size_t)blockIdx.x * blockDim.x + threadIdx.x;  // one float4 per thread
    float4 v = reinterpret_cast<const float4*>(x)[i];
    union { __half2 h; uint32_t u; } a, b;
    a.h = __floats2half2_rn(v.x, v.y);
    b.h = __floats2half2_rn(v.z, v.w);
    reinterpret_cast<uint2*>(g_x)[i] = make_uint2(a.u, b.u);
}

// ---------------- kernel 2: GPTQ dequant -> Wt (N,K) fp16, smem transpose ----
__global__ void dequant_kernel(const int* __restrict__ qweight,
                               const int* __restrict__ qzeros,
                               const float* __restrict__ scales) {
    __shared__ int tile[32][33];
    const int n0  = blockIdx.x * 32;   // 32 output columns (n)
    const int kb0 = blockIdx.y * 32;   // 32 packed k-rows (each = 8 k)
    const int t = threadIdx.x;

    #pragma unroll
    for (int it = 0; it < 4; it++) {           // coalesced read of qweight tile
        int idx = t + it * 256;
        int r = idx >> 5, c = idx & 31;
        tile[r][c] = qweight[(size_t)(kb0 + r) * NDIM + (n0 + c)];
    }
    __syncthreads();

    const int n_local = t >> 3;
    const int kb_sub  = t & 7;
    const int n = n0 + n_local;
    #pragma unroll
    for (int rr = 0; rr < 4; rr++) {
        int kb = kb_sub + rr * 8;
        int g  = (kb0 + kb) >> 4;              // 16 packed rows per group of 128
        float s = scales[g * NDIM + n];
        int z = (qzeros[g * (NDIM / 8) + (n >> 3)] >> ((n & 7) * 4)) & 0xF;
        float nsz = -s * (float)z;
        int qv = tile[kb][n_local];
        uint32_t w[4];
        #pragma unroll
        for (int j = 0; j < 4; j++) {
            float f0 = fmaf(s, (float)((qv >> (8 * j)) & 0xF), nsz);
            float f1 = fmaf(s, (float)((qv >> (8 * j + 4)) & 0xF), nsz);
            union { __half2 h; uint32_t u; } cv;
            cv.h = __floats2half2_rn(f0, f1);
            w[j] = cv.u;
        }
        // coalesced: 8 adjacent threads write 8 consecutive 16B chunks of row n
        *reinterpret_cast<uint4*>(&g_wt[(size_t)n * KDIM + (size_t)(kb0 + kb) * 8]) =
            make_uint4(w[0], w[1], w[2], w[3]);
    }
}

// ---------------- kernel 3: HMMA GEMM, cp.async 4-stage pipeline -------------
__global__ void __launch_bounds__(256)
gemm_hmma(const float* __restrict__ bias, float* __restrict__ out) {
    extern __shared__ __align__(128) char smem[];
    const uint32_t sb = smem_u32(smem);
    const int tid  = threadIdx.x;
    const int lane = tid & 31;
    const int w    = tid >> 5;
    const int wm   = w & 1;        // warp m index (0..1), warp tile 64 rows
    const int wn   = w >> 1;       // warp n index (0..3), warp tile 32 cols
    const int m0 = blockIdx.x * BM;
    const int n0 = blockIdx.y * BN;

    // ldmatrix lane addressing
    const int a_row  = lane & 15;                 // A: rows 0-15 of 16x16, k0/k8 by lane/16
    const int a_col  = (lane >> 4) * 8;
    const int b_noff = ((lane >> 4) & 1) * 8 + (lane & 7);  // B: x4 over 16 n
    const int b_koff = ((lane >> 3) & 1) * 8;

    float acc[4][4][4];
    #pragma unroll
    for (int mt = 0; mt < 4; mt++)
        #pragma unroll
        for (int nt = 0; nt < 4; nt++)
            #pragma unroll
            for (int q = 0; q < 4; q++) acc[mt][nt][q] = 0.f;

    // cp.async stage loader: 512 16B chunks per operand tile, 2 per thread
    auto load_stage = [&](int s, int kt) {
        const uint32_t abase = sb + s * STAGE_BYTES;
        const uint32_t bbase = abase + A_SM_BYTES;
        const int k0 = kt * BKQ;
        #pragma unroll
        for (int h = 0; h < 2; h++) {
            int c = tid + h * 256;
            int row = c >> 2, c16 = c & 3;
            cp_async16(abase + (uint32_t)(row * LDS_ROW + c16 * 8) * 2,
                       g_x  + (size_t)(m0 + row) * KDIM + k0 + c16 * 8);
            cp_async16(bbase + (uint32_t)(row * LDS_ROW + c16 * 8) * 2,
                       g_wt + (size_t)(n0 + row) * KDIM + k0 + c16 * 8);
        }
    };

    #pragma unroll
    for (int s = 0; s < STAGES - 1; s++) { load_stage(s, s); cp_commit(); }

    for (int kt = 0; kt < KITERS; kt++) {
        asm volatile("cp.async.wait_group %0;" :: "n"(STAGES - 2));
        __syncthreads();

        const int st = kt & (STAGES - 1);
        const uint32_t abase = sb + st * STAGE_BYTES;
        const uint32_t bbase = abase + A_SM_BYTES;

        #pragma unroll
        for (int ks = 0; ks < 2; ks++) {
            uint32_t ar[4][4], br[2][4];
            #pragma unroll
            for (int mt = 0; mt < 4; mt++)
                ldsm_x4(ar[mt], abase +
                    (uint32_t)((wm * 64 + mt * 16 + a_row) * LDS_ROW + ks * 16 + a_col) * 2);
            #pragma unroll
            for (int nt2 = 0; nt2 < 2; nt2++)
                ldsm_x4(br[nt2], bbase +
                    (uint32_t)((wn * 32 + nt2 * 16 + b_noff) * LDS_ROW + ks * 16 + b_koff) * 2);
            #pragma unroll
            for (int mt = 0; mt < 4; mt++)
                #pragma unroll
                for (int nt = 0; nt < 4; nt++)
                    mma16816(acc[mt][nt], ar[mt], &br[nt >> 1][(nt & 1) * 2]);
        }

        if (kt + STAGES - 1 < KITERS) load_stage((kt + STAGES - 1) & (STAGES - 1),
                                                 kt + STAGES - 1);
        cp_commit();   // empty groups at tail keep wait accounting uniform
    }

    // ---------------- epilogue: bias + fp32 stores ----------------
    const int r0 = lane >> 2;
    const int cq = (lane & 3) * 2;
    const int ncol = n0 + wn * 32;
    float bv[4][2];
    #pragma unroll
    for (int nt = 0; nt < 4; nt++) {
        bv[nt][0] = bias[ncol + nt * 8 + cq];
        bv[nt][1] = bias[ncol + nt * 8 + cq + 1];
    }
    #pragma unroll
    for (int mt = 0; mt < 4; mt++) {
        #pragma unroll
        for (int h = 0; h < 2; h++) {
            const size_t row = (size_t)m0 + wm * 64 + mt * 16 + r0 + h * 8;
            float* op = out + row * NDIM + ncol;
            #pragma unroll
            for (int nt = 0; nt < 4; nt++) {
                float2 v;
                v.x = acc[mt][nt][h * 2 + 0] + bv[nt][0];
                v.y = acc[mt][nt][h * 2 + 1] + bv[nt][1];
                *reinterpret_cast<float2*>(op + nt * 8 + cq) = v;
            }
        }
    }
}

// ---------------- host ----------------
extern "C" void kernel_launch(void* const* d_in, const int* in_sizes, int n_in,
                              void* d_out, int out_size) {
    const float* x       = (const float*)d_in[0];
    const int*   qweight = (const int*)d_in[1];
    const int*   qzeros  = (const int*)d_in[2];
    const float* scales  = (const float*)d_in[3];
    const float* bias    = (const float*)d_in[4];
    float* out = (float*)d_out;

    convert_x_kernel<<<(MDIM * (size_t)KDIM / 4) / 256, 256>>>(x);
    dequant_kernel<<<dim3(NDIM / 32, (KDIM / 8) / 32), 256>>>(qweight, qzeros, scales);

    // No static guard (harness forbids call-count-dependent behavior);
    // cudaFuncSetAttribute is not a stream op, safe under graph capture.
    cudaFuncSetAttribute(gemm_hmma, cudaFuncAttributeMaxDynamicSharedMemorySize,
                         SMEM_TOTAL);
    // m-tiles fastest: one wave spans all of A (67MB fp16) -> A stays L2-resident
    gemm_hmma<<<dim3(MDIM / BM, NDIM / BN), 256, SMEM_TOTAL>>>(bias, out);
}